// round 10
// baseline (speedup 1.0000x reference)
#include <cuda_runtime.h>

// LoCon1d: out[b][o][s] = sum_{c,k} in[b][c][s+k-1] * w[o][c][s][k] + bias[o][s]
// B=16, Cin=64, Cout=64, S=1024, K=3 (zero pad)
//
//  1) transpose_kernel: input (B,C,S) -> g_trans[c][1+s][b], zero halo rows
//  2) locon1d_kernel:   warp-private cp.async weight rings, ONE __syncthreads
//                       total; per-warp wait_group + __syncwarp only.

#define S_LEN   1024
#define CIN     64
#define COUT    64
#define BATCH   16
#define KW      3
#define S_TILE  16
#define O_TILE  16
#define HALO    (S_TILE + 2)        // 18
#define THREADS 256

// transposed input: [c][j=0..1025][b=0..15], j = s+1 (rows 0 and 1025 zero)
#define TR_J    (S_LEN + 2)
__device__ float g_trans[CIN * TR_J * BATCH];

// input tile in shared: stride-5 pad -> row (c,j) at f4 idx 5*(c*18+j)+bq
#define ROW4     5
#define IN4_CNT  (CIN * HALO * ROW4)        // 5760 f4
#define IN_BYTES (IN4_CNT * 16)             // 92160 B
// warp-private weight rings: 8 warps x 8 stages x 384B (2 couts x 16s x 3k f32)
#define W_STAGE_B   384
#define N_STAGES    8
#define WRING_B     (N_STAGES * W_STAGE_B)                // 3072 per warp
#define SMEM_BYTES  (IN_BYTES + 8 * WRING_B)              // 116736

typedef unsigned long long u64;

__device__ __forceinline__ u64 splat2(float w) {
    u64 r;
    asm("mov.b64 %0, {%1, %1};" : "=l"(r) : "f"(w));
    return r;
}
__device__ __forceinline__ void fma2(u64 &d, u64 a, u64 b) {
    asm("fma.rn.f32x2 %0, %1, %2, %0;" : "+l"(d) : "l"(a), "l"(b));
}
__device__ __forceinline__ float2 u2f(u64 u) {
    float2 r;
    asm("mov.b64 {%0, %1}, %2;" : "=f"(r.x), "=f"(r.y) : "l"(u));
    return r;
}
__device__ __forceinline__ void cp16(unsigned dst, const void* src) {
    asm volatile("cp.async.cg.shared.global [%0], [%1], 16;" :: "r"(dst), "l"(src));
}
__device__ __forceinline__ void cp_commit() {
    asm volatile("cp.async.commit_group;");
}
__device__ __forceinline__ void cp_wait6() {
    asm volatile("cp.async.wait_group 6;");
}
__device__ __forceinline__ void cp_wait7() {
    asm volatile("cp.async.wait_group 7;");
}

#define WF(warr, i) (((i) & 3) == 0 ? (warr)[(i) >> 2].x : \
                     ((i) & 3) == 1 ? (warr)[(i) >> 2].y : \
                     ((i) & 3) == 2 ? (warr)[(i) >> 2].z : (warr)[(i) >> 2].w)

// ---------------------------------------------------------------------------
// transpose: input[b][c][s] -> g_trans[c][1+s][b]; zero rows j=0 and j=1025
// ---------------------------------------------------------------------------
__global__ void __launch_bounds__(256)
transpose_kernel(const float* __restrict__ input)
{
    __shared__ float tile[BATCH][65];

    const int c  = blockIdx.x;
    const int s0 = blockIdx.y * 64;
    const int tid = threadIdx.x;

    #pragma unroll
    for (int r = 0; r < 4; ++r) {
        const int idx = tid + r * 256;
        const int b  = idx >> 6;
        const int sl = idx & 63;
        tile[b][sl] = input[((size_t)b * CIN + c) * S_LEN + s0 + sl];
    }
    __syncthreads();

    #pragma unroll
    for (int r = 0; r < 4; ++r) {
        const int idx = tid + r * 256;
        const int b  = idx & 15;
        const int sl = idx >> 4;
        g_trans[((size_t)c * TR_J + 1 + s0 + sl) * BATCH + b] = tile[b][sl];
    }

    if (blockIdx.x == 0 && blockIdx.y == 0) {
        for (int e = tid; e < CIN * BATCH; e += 256) {
            const int cc = e >> 4, bb = e & 15;
            g_trans[((size_t)cc * TR_J + 0) * BATCH + bb]        = 0.f;
            g_trans[((size_t)cc * TR_J + TR_J - 1) * BATCH + bb] = 0.f;
        }
    }
}

// ---------------------------------------------------------------------------
// main conv: 8 warps, warp w owns couts {o0+2w, o0+2w+1} and its own ring
// ---------------------------------------------------------------------------
__global__ void __launch_bounds__(THREADS, 1)
locon1d_kernel(const float* __restrict__ weight,
               const float* __restrict__ bias,
               float* __restrict__ out)
{
    extern __shared__ float4 sh4[];

    const int s0 = blockIdx.x * S_TILE;
    const int o0 = blockIdx.y * O_TILE;
    const int tid  = threadIdx.x;
    const int wrp  = tid >> 5;
    const int lane = tid & 31;
    const unsigned sh_u = (unsigned)__cvta_generic_to_shared(sh4);

    // ---- group 0: input tile fill via cp.async (18 f4 per thread) ---------
    // logical idx -> (c = idx/72, j = (idx>>2)%18, bq = idx&3)
    // dst f4 = 5*(idx>>2) + bq ; src = g_trans[(c*TR_J + s0 + j)*16 + bq*4]
    #pragma unroll
    for (int r = 0; r < 18; ++r) {
        const int idx = tid + r * 256;          // < 4608
        const int bq = idx & 3;
        const int t  = idx >> 2;
        const int j  = t % 18;
        const int c  = t / 18;
        const unsigned dst = sh_u + (unsigned)((5 * t + bq) * 16);
        const float* src = g_trans + ((size_t)c * TR_J + s0 + j) * BATCH + bq * 4;
        cp16(dst, src);
    }
    cp_commit();                                 // group 0

    // ---- warp-private weight ring ----------------------------------------
    // lane l < 24 copies f4 l%12 of cout (o0+2w+(l>=12)) for channel c
    const int l12 = (lane < 12) ? lane : lane - 12;
    const int ocp = o0 + 2 * wrp + (lane >= 12 ? 1 : 0);
    const float* wsrc = weight + ((size_t)ocp * CIN) * (S_LEN * 3)
                               + (size_t)s0 * 3 + l12 * 4;
    const unsigned wring = sh_u + (unsigned)(IN_BYTES + wrp * WRING_B);
    const unsigned wdst_off = (unsigned)(l12 * 16 + (lane >= 12 ? 192 : 0));

    auto WISSUE = [&](int c) {
        if (lane < 24)
            cp16(wring + (unsigned)((c & (N_STAGES - 1)) * W_STAGE_B) + wdst_off,
                 wsrc + (size_t)c * (S_LEN * 3));
        cp_commit();
    };

    // prologue: groups 1..7 = weight stages 0..6
    WISSUE(0); WISSUE(1); WISSUE(2); WISSUE(3); WISSUE(4); WISSUE(5); WISSUE(6);

    // input group complete (completed >= 1), then ONE block barrier
    cp_wait7();
    __syncthreads();          // the only __syncthreads in the kernel

    // ---- compute mapping --------------------------------------------------
    const int bg = lane & 3;
    const int sg = (lane >> 2) & 3;
    const int oh = lane >> 4;
    const int o     = o0 + 2 * wrp + oh;
    const int sbase = s0 + sg * 4;

    const ulonglong2* shp2 = reinterpret_cast<const ulonglong2*>(sh4);
    const int vofs = ROW4 * (4 * sg) + bg;       // + 90 per c, + 5 per d
    // weight LDS f4 index inside stage (base f4 ≡ 0 mod 8):
    // quads {12oh+3sg} mod 8 = 8 distinct -> conflict-free with bg broadcast
    const float4* wbase = reinterpret_cast<const float4*>(
        reinterpret_cast<const char*>(sh4) + IN_BYTES + wrp * WRING_B);
    const int wofs = oh * 12 + 3 * sg;

    u64 acc[4][2];
    #pragma unroll
    for (int j = 0; j < 4; ++j) { acc[j][0] = 0ull; acc[j][1] = 0ull; }

    for (int c = 0; c < CIN; ++c) {
        // commits so far = 8 + c; wait6 -> completed >= c+2 -> stage c done
        cp_wait6();
        __syncwarp();        // other lanes' cp16s of this stage visible

        const float4* stg = wbase + (c & (N_STAGES - 1)) * (W_STAGE_B / 16);
        float4 wa[3];
        #pragma unroll
        for (int i = 0; i < 3; ++i)
            wa[i] = stg[wofs + i];

        ulonglong2 v[6];
        const int base = 90 * c + vofs;
        #pragma unroll
        for (int d = 0; d < 6; ++d)
            v[d] = shp2[base + 5 * d];

        #pragma unroll
        for (int ss = 0; ss < 4; ++ss) {
            #pragma unroll
            for (int k = 0; k < KW; ++k) {
                const int d  = ss + k;
                const int wi = ss * 3 + k;
                const u64 w2 = splat2(WF(wa, wi));
                fma2(acc[ss][0], v[d].x, w2);
                fma2(acc[ss][1], v[d].y, w2);
            }
        }

        __syncwarp();        // all lanes done reading slot (c-1)&7 ring area
        // refill stage c+7 -> slot (c-1)&7 (warp-private, just released)
        if (c + 7 < CIN) WISSUE(c + 7); else cp_commit();
    }

    // ---- epilogue: bias + store ------------------------------------------
    {
        const float4 bz = *reinterpret_cast<const float4*>(bias + (size_t)o * S_LEN + sbase);
        #pragma unroll
        for (int pr = 0; pr < 2; ++pr) {
            const float2 f0 = u2f(acc[0][pr]);
            const float2 f1 = u2f(acc[1][pr]);
            const float2 f2 = u2f(acc[2][pr]);
            const float2 f3 = u2f(acc[3][pr]);
            const int b0 = bg * 4 + pr * 2;
            float4 r0 = make_float4(f0.x + bz.x, f1.x + bz.y, f2.x + bz.z, f3.x + bz.w);
            float4 r1 = make_float4(f0.y + bz.x, f1.y + bz.y, f2.y + bz.z, f3.y + bz.w);
            *reinterpret_cast<float4*>(out + ((size_t)(b0 * COUT + o)) * S_LEN + sbase) = r0;
            *reinterpret_cast<float4*>(out + ((size_t)((b0 + 1) * COUT + o)) * S_LEN + sbase) = r1;
        }
    }
}

extern "C" void kernel_launch(void* const* d_in, const int* in_sizes, int n_in,
                              void* d_out, int out_size) {
    const float* input  = (const float*)d_in[0];
    const float* weight = (const float*)d_in[1];
    const float* bias   = (const float*)d_in[2];
    float* out = (float*)d_out;

    cudaFuncSetAttribute(locon1d_kernel,
                         cudaFuncAttributeMaxDynamicSharedMemorySize, SMEM_BYTES);

    dim3 tgrid(CIN, S_LEN / 64);                 // (64, 16)
    transpose_kernel<<<tgrid, 256>>>(input);

    dim3 grid(S_LEN / S_TILE, COUT / O_TILE);    // (64, 4)
    locon1d_kernel<<<grid, THREADS, SMEM_BYTES>>>(weight, bias, out);
}